// round 2
// baseline (speedup 1.0000x reference)
#include <cuda_runtime.h>
#include <math.h>
#include <stdint.h>

// Problem constants
#define R_      2
#define CH_     2
#define NNODES  20000
#define EEDGES  100000
#define C_      256
#define ED_     16
#define MROWS   (R_*CH_*NNODES)   // 80000
#define RCSLICE ((size_t)NNODES * C_)

// Scratch (static device globals; no allocation at runtime)
__device__ float g_xl[(size_t)MROWS * C_];    // x @ lin_W + lin_b
__device__ float g_sums[(size_t)MROWS * C_];  // scatter-add accumulator
__device__ float g_cnt[NNODES];
__device__ float g_invc[NNODES];
__device__ int   g_src[EEDGES];
__device__ int   g_dst[EEDGES];
__device__ int   g_is64;

// ---------------------------------------------------------------------------
// edge_index dtype detection: reference requests int64 but JAX default
// (x64 disabled) delivers int32. Sniff the safe prefix: for LE int64 with
// values < 2^31, all odd int32 words are 0.
// ---------------------------------------------------------------------------
__global__ void detect_kernel(const int* __restrict__ eidx_raw) {
    if (threadIdx.x == 0 && blockIdx.x == 0) {
        int all_zero = 1;
        for (int i = 1; i < 64; i += 2)
            if (eidx_raw[i] != 0) { all_zero = 0; break; }
        g_is64 = all_zero;
    }
}

__global__ void convert_idx_kernel(const int* __restrict__ eidx_raw) {
    int e = blockIdx.x * blockDim.x + threadIdx.x;
    if (e >= EEDGES) return;
    if (g_is64) {
        g_src[e] = eidx_raw[2 * e];
        g_dst[e] = eidx_raw[2 * (EEDGES + e)];
    } else {
        g_src[e] = eidx_raw[e];
        g_dst[e] = eidx_raw[EEDGES + e];
    }
}

// ---------------------------------------------------------------------------
// Zero scratch
// ---------------------------------------------------------------------------
__global__ void zero_kernel() {
    size_t i = (size_t)blockIdx.x * blockDim.x + threadIdx.x;
    size_t n4 = (size_t)MROWS * C_ / 4;
    if (i < n4) ((float4*)g_sums)[i] = make_float4(0.f, 0.f, 0.f, 0.f);
    if (i < NNODES) g_cnt[i] = 0.f;
}

// ---------------------------------------------------------------------------
// In-degree count + reciprocal
// ---------------------------------------------------------------------------
__global__ void count_kernel() {
    int e = blockIdx.x * blockDim.x + threadIdx.x;
    if (e < EEDGES) {
        int dst = g_dst[e];
        if (dst >= 0 && dst < NNODES) atomicAdd(&g_cnt[dst], 1.0f);
    }
}

__global__ void finalize_cnt_kernel() {
    int n = blockIdx.x * blockDim.x + threadIdx.x;
    if (n < NNODES) g_invc[n] = 1.0f / fmaxf(g_cnt[n], 1.0f);
}

// ---------------------------------------------------------------------------
// GEMM 1: g_xl = x @ lin_W + lin_b      (M=80000, N=256, K=256, fp32)
// 128x128 block tile, 16 K-slab, 256 threads, 8x8 microtile.
// ---------------------------------------------------------------------------
__global__ __launch_bounds__(256, 2)
void gemm_xl_kernel(const float* __restrict__ A,
                    const float* __restrict__ W,
                    const float* __restrict__ bias) {
    __shared__ float As[16][128];  // A transposed: As[k][m]
    __shared__ float Bs[16][128];  // Bs[k][n]

    const int bm = blockIdx.x * 128;
    const int bn = blockIdx.y * 128;
    const int t  = threadIdx.x;
    const int tx = t & 15;
    const int ty = t >> 4;

    const int arow = t >> 1;            // row within A tile this thread loads
    const int acolbase = (t & 1) * 8;   // starting col (of 16) in the K slab

    float acc[8][8];
#pragma unroll
    for (int m = 0; m < 8; m++)
#pragma unroll
        for (int n = 0; n < 8; n++) acc[m][n] = 0.f;

    for (int kt = 0; kt < 256; kt += 16) {
        // Load A tile (transposed into smem)
#pragma unroll
        for (int i = 0; i < 2; i++) {
            int c4 = acolbase + i * 4;
            float4 v = *(const float4*)&A[(size_t)(bm + arow) * 256 + kt + c4];
            As[c4 + 0][arow] = v.x;
            As[c4 + 1][arow] = v.y;
            As[c4 + 2][arow] = v.z;
            As[c4 + 3][arow] = v.w;
        }
        // Load B tile
#pragma unroll
        for (int i = 0; i < 2; i++) {
            int n4 = tx * 8 + i * 4;
            *(float4*)&Bs[ty][n4] = *(const float4*)&W[(size_t)(kt + ty) * 256 + bn + n4];
        }
        __syncthreads();

#pragma unroll
        for (int k = 0; k < 16; k++) {
            float a[8], b[8];
            *(float4*)&a[0] = *(const float4*)&As[k][ty * 8];
            *(float4*)&a[4] = *(const float4*)&As[k][ty * 8 + 4];
            *(float4*)&b[0] = *(const float4*)&Bs[k][tx * 8];
            *(float4*)&b[4] = *(const float4*)&Bs[k][tx * 8 + 4];
#pragma unroll
            for (int m = 0; m < 8; m++)
#pragma unroll
                for (int n = 0; n < 8; n++) acc[m][n] = fmaf(a[m], b[n], acc[m][n]);
        }
        __syncthreads();
    }

    // Epilogue: add bias, store
    float bv[8];
#pragma unroll
    for (int n = 0; n < 8; n++) bv[n] = __ldg(&bias[bn + tx * 8 + n]);
#pragma unroll
    for (int m = 0; m < 8; m++) {
        size_t gr = (size_t)(bm + ty * 8 + m);
#pragma unroll
        for (int n = 0; n < 8; n += 4) {
            float4 v;
            v.x = acc[m][n + 0] + bv[n + 0];
            v.y = acc[m][n + 1] + bv[n + 1];
            v.z = acc[m][n + 2] + bv[n + 2];
            v.w = acc[m][n + 3] + bv[n + 3];
            *(float4*)&g_xl[gr * 256 + bn + tx * 8 + n] = v;
        }
    }
}

// ---------------------------------------------------------------------------
// Scatter: msg = gelu(x_l[src] + bond(edge_attr)) * w  -> atomicAdd sums[dst]
// One block = 32 edges x 256 channels. bond_W cached in smem; bond column in regs.
// ---------------------------------------------------------------------------
#define EPB 32
__global__ __launch_bounds__(256)
void scatter_kernel(const float* __restrict__ edge_attr,
                    const float* __restrict__ ew,
                    const float* __restrict__ bondW,
                    const float* __restrict__ bondb) {
    __shared__ float sBW[ED_ * C_];      // 16 KB
    __shared__ float sEA[EPB][ED_];      // 2 KB
    __shared__ int   sSrc[EPB];
    __shared__ int   sDst[EPB];
    __shared__ float sW[4][EPB];

    const int t  = threadIdx.x;
    const int e0 = blockIdx.x * EPB;

    for (int i = t; i < ED_ * C_; i += 256) sBW[i] = bondW[i];
    if (t < EPB) {
        int e = e0 + t;
        sSrc[t] = g_src[e];
        sDst[t] = g_dst[e];
#pragma unroll
        for (int rc = 0; rc < 4; rc++) sW[rc][t] = ew[(size_t)rc * EEDGES + e];
    }
    for (int i = t; i < EPB * ED_; i += 256)
        ((float*)sEA)[i] = edge_attr[(size_t)e0 * ED_ + i];
    __syncthreads();

    const int c = t;  // channel 0..255
    float bw[ED_];
#pragma unroll
    for (int k = 0; k < ED_; k++) bw[k] = sBW[k * C_ + c];
    const float bb = __ldg(&bondb[c]);

    for (int j = 0; j < EPB; j++) {
        float emb = bb;
#pragma unroll
        for (int k = 0; k < ED_; k++) emb = fmaf(sEA[j][k], bw[k], emb);
        const int src = sSrc[j];
        const int dst = sDst[j];
        if ((unsigned)src >= NNODES || (unsigned)dst >= NNODES) continue;
#pragma unroll
        for (int rc = 0; rc < 4; rc++) {
            size_t base = (size_t)rc * RCSLICE;
            float v = g_xl[base + (size_t)src * C_ + c] + emb;
            // exact GELU: 0.5*v*(1+erf(v/sqrt(2)))
            float g = 0.5f * v * (1.0f + erff(v * 0.70710678118654752f));
            atomicAdd(&g_sums[base + (size_t)dst * C_ + c], g * sW[rc][j]);
        }
    }
}

// ---------------------------------------------------------------------------
// GEMM 2 (fused epilogue):
// out = (g_sums * invcnt) @ linl_W + linl_b + x @ linr_W
// Implemented as one K=512 GEMM: first 256 K from scaled sums/Wl,
// next 256 K from x/Wr.
// ---------------------------------------------------------------------------
__global__ __launch_bounds__(256, 2)
void gemm_epi_kernel(const float* __restrict__ x,
                     const float* __restrict__ Wl,
                     const float* __restrict__ bl,
                     const float* __restrict__ Wr,
                     float* __restrict__ out) {
    __shared__ float As[16][128];
    __shared__ float Bs[16][128];

    const int bm = blockIdx.x * 128;
    const int bn = blockIdx.y * 128;
    const int t  = threadIdx.x;
    const int tx = t & 15;
    const int ty = t >> 4;

    const int arow = t >> 1;
    const int acolbase = (t & 1) * 8;
    const float invsc = g_invc[(bm + arow) % NNODES];  // row -> node = row % N

    float acc[8][8];
#pragma unroll
    for (int m = 0; m < 8; m++)
#pragma unroll
        for (int n = 0; n < 8; n++) acc[m][n] = 0.f;

    for (int kt = 0; kt < 512; kt += 16) {
        const bool first = (kt < 256);
        const int kk = first ? kt : (kt - 256);
        const float* Ap = first ? g_sums : x;
        const float* Bp = first ? Wl : Wr;
        const float sc = first ? invsc : 1.0f;

#pragma unroll
        for (int i = 0; i < 2; i++) {
            int c4 = acolbase + i * 4;
            float4 v = *(const float4*)&Ap[(size_t)(bm + arow) * 256 + kk + c4];
            As[c4 + 0][arow] = v.x * sc;
            As[c4 + 1][arow] = v.y * sc;
            As[c4 + 2][arow] = v.z * sc;
            As[c4 + 3][arow] = v.w * sc;
        }
#pragma unroll
        for (int i = 0; i < 2; i++) {
            int n4 = tx * 8 + i * 4;
            *(float4*)&Bs[ty][n4] = *(const float4*)&Bp[(size_t)(kk + ty) * 256 + bn + n4];
        }
        __syncthreads();

#pragma unroll
        for (int k = 0; k < 16; k++) {
            float a[8], b[8];
            *(float4*)&a[0] = *(const float4*)&As[k][ty * 8];
            *(float4*)&a[4] = *(const float4*)&As[k][ty * 8 + 4];
            *(float4*)&b[0] = *(const float4*)&Bs[k][tx * 8];
            *(float4*)&b[4] = *(const float4*)&Bs[k][tx * 8 + 4];
#pragma unroll
            for (int m = 0; m < 8; m++)
#pragma unroll
                for (int n = 0; n < 8; n++) acc[m][n] = fmaf(a[m], b[n], acc[m][n]);
        }
        __syncthreads();
    }

    float bv[8];
#pragma unroll
    for (int n = 0; n < 8; n++) bv[n] = __ldg(&bl[bn + tx * 8 + n]);
#pragma unroll
    for (int m = 0; m < 8; m++) {
        size_t gr = (size_t)(bm + ty * 8 + m);
#pragma unroll
        for (int n = 0; n < 8; n += 4) {
            float4 v;
            v.x = acc[m][n + 0] + bv[n + 0];
            v.y = acc[m][n + 1] + bv[n + 1];
            v.z = acc[m][n + 2] + bv[n + 2];
            v.w = acc[m][n + 3] + bv[n + 3];
            *(float4*)&out[gr * 256 + bn + tx * 8 + n] = v;
        }
    }
}

// ---------------------------------------------------------------------------
// Launch
// ---------------------------------------------------------------------------
extern "C" void kernel_launch(void* const* d_in, const int* in_sizes, int n_in,
                              void* d_out, int out_size) {
    const float* x     = (const float*)d_in[0];
    const float* eattr = (const float*)d_in[1];
    const float* ew    = (const float*)d_in[2];
    const float* linW  = (const float*)d_in[3];
    const float* linb  = (const float*)d_in[4];
    const float* linlW = (const float*)d_in[5];
    const float* linlb = (const float*)d_in[6];
    const float* linrW = (const float*)d_in[7];
    const float* bondW = (const float*)d_in[8];
    const float* bondb = (const float*)d_in[9];
    const int*   eidx  = (const int*)d_in[10];   // int32 or int64 (sniffed)
    float*       out   = (float*)d_out;

    // 0. detect edge_index dtype + canonicalize to int32
    detect_kernel<<<1, 32>>>(eidx);
    convert_idx_kernel<<<(EEDGES + 255) / 256, 256>>>(eidx);

    // 1. zero sums + counts
    {
        size_t n4 = (size_t)MROWS * C_ / 4;  // 5,120,000
        int blocks = (int)((n4 + 255) / 256);
        zero_kernel<<<blocks, 256>>>();
    }

    // 2. x_l = x @ lin_W + lin_b
    {
        dim3 grid(MROWS / 128, C_ / 128);
        gemm_xl_kernel<<<grid, 256>>>(x, linW, linb);
    }

    // 3. in-degree counts -> reciprocals
    count_kernel<<<(EEDGES + 255) / 256, 256>>>();
    finalize_cnt_kernel<<<(NNODES + 255) / 256, 256>>>();

    // 4. gather + bond-encode + gelu + weighted scatter-add
    scatter_kernel<<<EEDGES / EPB, 256>>>(eattr, ew, bondW, bondb);

    // 5. out = (sums/cnt) @ linl_W + linl_b + x @ linr_W
    {
        dim3 grid(MROWS / 128, C_ / 128);
        gemm_epi_kernel<<<grid, 256>>>(x, linlW, linlb, linrW, out);
    }
}

// round 9
// speedup vs baseline: 2.0447x; 2.0447x over previous
#include <cuda_runtime.h>
#include <math.h>
#include <stdint.h>

// Problem constants
#define R_      2
#define CH_     2
#define NNODES  20000
#define EEDGES  100000
#define C_      256
#define ED_     16
#define MROWS   (R_*CH_*NNODES)   // 80000
#define RCSLICE ((size_t)NNODES * C_)

// Scratch (static device globals; no allocation at runtime)
__device__ float g_xl[(size_t)MROWS * C_];    // x @ lin_W + lin_b
__device__ float g_sums[(size_t)MROWS * C_];  // scatter-add accumulator
__device__ float g_cnt[NNODES];
__device__ float g_invc[NNODES];
__device__ int   g_src[EEDGES];
__device__ int   g_dst[EEDGES];
__device__ int   g_is64;
// Fragment-ordered weight images for mma.sync tf32 B operand
__device__ float g_w0fr[256 * 256];  // lin_W
__device__ float g_w1fr[256 * 256];  // linl_W
__device__ float g_w2fr[256 * 256];  // linr_W

__device__ __forceinline__ float tf32rn(float x) {
    uint32_t r;
    asm("cvt.rna.tf32.f32 %0, %1;" : "=r"(r) : "f"(x));
    return __uint_as_float(r);
}

__device__ __forceinline__ void mma_tf32(float* d, const float* a, const float* b) {
    asm volatile(
        "mma.sync.aligned.m16n8k8.row.col.f32.tf32.tf32.f32 "
        "{%0,%1,%2,%3}, {%4,%5,%6,%7}, {%8,%9}, {%0,%1,%2,%3};\n"
        : "+f"(d[0]), "+f"(d[1]), "+f"(d[2]), "+f"(d[3])
        : "r"(__float_as_uint(a[0])), "r"(__float_as_uint(a[1])),
          "r"(__float_as_uint(a[2])), "r"(__float_as_uint(a[3])),
          "r"(__float_as_uint(b[0])), "r"(__float_as_uint(b[1])));
}

// ---------------------------------------------------------------------------
// edge_index dtype detection (JAX x64-off delivers int32 despite int64 request)
// ---------------------------------------------------------------------------
__global__ void detect_kernel(const int* __restrict__ eidx_raw) {
    if (threadIdx.x == 0 && blockIdx.x == 0) {
        int all_zero = 1;
        for (int i = 1; i < 64; i += 2)
            if (eidx_raw[i] != 0) { all_zero = 0; break; }
        g_is64 = all_zero;
    }
}
// convert + in-degree count fused
__global__ void convert_idx_kernel(const int* __restrict__ eidx_raw) {
    int e = blockIdx.x * blockDim.x + threadIdx.x;
    if (e >= EEDGES) return;
    int s, d;
    if (g_is64) {
        s = eidx_raw[2 * e];
        d = eidx_raw[2 * (EEDGES + e)];
    } else {
        s = eidx_raw[e];
        d = eidx_raw[EEDGES + e];
    }
    g_src[e] = s;
    g_dst[e] = d;
    if (d >= 0 && d < NNODES) atomicAdd(&g_cnt[d], 1.0f);
}

__global__ void zero_kernel() {
    size_t i = (size_t)blockIdx.x * blockDim.x + threadIdx.x;
    size_t n4 = (size_t)MROWS * C_ / 4;
    if (i < n4) ((float4*)g_sums)[i] = make_float4(0.f, 0.f, 0.f, 0.f);
    if (i < NNODES) g_cnt[i] = 0.f;
}
__global__ void finalize_cnt_kernel() {
    int n = blockIdx.x * blockDim.x + threadIdx.x;
    if (n < NNODES) g_invc[n] = 1.0f / fmaxf(g_cnt[n], 1.0f);
}

// ---------------------------------------------------------------------------
// Weight prep: W[k][n] (K=256 x N=256 row-major) -> mma B-fragment order.
// For element (k,n): nb=n>>7, n_l=n&127, natom=n_l>>3, nr=n_l&7,
//                    k8=k>>3, kr=k&7, lane=nr*4+(kr&3), reg=kr>>2
// idx = (((nb*32 + k8)*16 + natom)*32 + lane)*2 + reg
// ---------------------------------------------------------------------------
__global__ void prep_w_kernel(const float* __restrict__ W, float* __restrict__ dst) {
    int e = blockIdx.x * blockDim.x + threadIdx.x;
    if (e >= 256 * 256) return;
    int n = e & 255, k = e >> 8;
    int nb = n >> 7, n_l = n & 127, natom = n_l >> 3, nr = n_l & 7;
    int k8 = k >> 3, kr = k & 7;
    int lane = nr * 4 + (kr & 3), reg = kr >> 2;
    int idx = (((nb * 32 + k8) * 16 + natom) * 32 + lane) * 2 + reg;
    dst[idx] = tf32rn(W[e]);
}

// ---------------------------------------------------------------------------
// mma.sync tf32 GEMM. CTA tile 128(M) x 128(N), 8 warps = 4m x 2n,
// warp tile 32x64, k-slab 16, double buffered.
// mode 0: out = A0 @ W0 + bias               (K=256)
// mode 1: out = (A0*invc) @ W0 + A1 @ W1 + bias   (K=512, two segments)
// ---------------------------------------------------------------------------
#define ASTRIDE 20   // floats per A smem row (16 + 4 pad, conflict-free quads)

__global__ __launch_bounds__(256, 2)
void mma_gemm_kernel(const float* __restrict__ A0, const float* __restrict__ W0fr,
                     const float* __restrict__ A1, const float* __restrict__ W1fr,
                     const float* __restrict__ bias, float* __restrict__ out, int mode) {
    __shared__ float As[2][128 * ASTRIDE];   // 20480 B
    __shared__ float Bs[2][2048];            // 16384 B
    __shared__ float sBias[128];

    const int t    = threadIdx.x;
    const int lane = t & 31;
    const int wid  = t >> 5;
    const int wm   = wid & 3;       // warp m index (0..3)
    const int wn   = wid >> 2;      // warp n index (0..1)
    const int bm   = blockIdx.x * 128;
    const int bn   = blockIdx.y * 128;
    const int nb   = blockIdx.y;    // n-block for fragment image

    if (t < 128) sBias[t] = bias[bn + t];

    const int arow  = t >> 1;       // 0..127
    const int ahalf = t & 1;        // which 8-k half of the 16-k slab

    float acc[2][8][4];
#pragma unroll
    for (int i = 0; i < 2; i++)
#pragma unroll
        for (int j = 0; j < 8; j++)
#pragma unroll
            for (int q = 0; q < 4; q++) acc[i][j][q] = 0.f;

    const int NK = mode ? 32 : 16;  // 16-k slabs total

    // prologue: slab 0
    {
        const float* Aseg = A0;
        const float* Wfr = W0fr;
        bool scaled = (mode == 1);
        const float* srcA = &Aseg[(size_t)(bm + arow) * 256 + ahalf * 8];
        float4 v1 = *(const float4*)(srcA);
        float4 v2 = *(const float4*)(srcA + 4);
        if (scaled) {
            float sc = g_invc[(bm + arow) % NNODES];
            v1.x *= sc; v1.y *= sc; v1.z *= sc; v1.w *= sc;
            v2.x *= sc; v2.y *= sc; v2.z *= sc; v2.w *= sc;
        }
        v1.x = tf32rn(v1.x); v1.y = tf32rn(v1.y); v1.z = tf32rn(v1.z); v1.w = tf32rn(v1.w);
        v2.x = tf32rn(v2.x); v2.y = tf32rn(v2.y); v2.z = tf32rn(v2.z); v2.w = tf32rn(v2.w);
        *(float4*)&As[0][arow * ASTRIDE + ahalf * 8]     = v1;
        *(float4*)&As[0][arow * ASTRIDE + ahalf * 8 + 4] = v2;
        const float4* srcB = (const float4*)&Wfr[(size_t)(nb * 32 + 0) * 1024];
        ((float4*)Bs[0])[t]       = srcB[t];
        ((float4*)Bs[0])[t + 256] = srcB[t + 256];
    }
    __syncthreads();

    for (int kt = 0; kt < NK; kt++) {
        const int cur = kt & 1;

        // prefetch next slab into registers
        float4 pA1, pA2, pB1, pB2;
        bool have_next = (kt + 1 < NK);
        float nsc = 1.0f;
        if (have_next) {
            int kn = kt + 1;
            int seg = (mode == 1) ? (kn >> 4) : 0;
            int ktl = (mode == 1) ? (kn & 15) : kn;
            const float* Aseg = (seg == 0) ? A0 : A1;
            const float* Wfr = (seg == 0) ? W0fr : W1fr;
            bool scaled = (mode == 1 && seg == 0);
            const float* srcA = &Aseg[(size_t)(bm + arow) * 256 + ktl * 16 + ahalf * 8];
            pA1 = *(const float4*)(srcA);
            pA2 = *(const float4*)(srcA + 4);
            if (scaled) nsc = g_invc[(bm + arow) % NNODES];
            const float4* srcB = (const float4*)&Wfr[(size_t)(nb * 32 + ktl * 2) * 1024];
            pB1 = srcB[t];
            pB2 = srcB[t + 256];
        }

        // compute on current buffer
#pragma unroll
        for (int ka = 0; ka < 2; ka++) {
            float bfr[8][2];
#pragma unroll
            for (int n8 = 0; n8 < 8; n8++) {
                const float2 bv = *(const float2*)&Bs[cur][((ka * 16 + wn * 8 + n8) * 32 + lane) * 2];
                bfr[n8][0] = bv.x; bfr[n8][1] = bv.y;
            }
#pragma unroll
            for (int m2 = 0; m2 < 2; m2++) {
                float afr[4];
                const int r0 = wm * 32 + m2 * 16 + (lane >> 2);
                const int k0 = ka * 8 + (lane & 3);
                afr[0] = As[cur][r0 * ASTRIDE + k0];
                afr[1] = As[cur][(r0 + 8) * ASTRIDE + k0];
                afr[2] = As[cur][r0 * ASTRIDE + k0 + 4];
                afr[3] = As[cur][(r0 + 8) * ASTRIDE + k0 + 4];
#pragma unroll
                for (int n8 = 0; n8 < 8; n8++)
                    mma_tf32(acc[m2][n8], afr, bfr[n8]);
            }
        }

        // store prefetched slab
        if (have_next) {
            const int nxt = cur ^ 1;
            pA1.x *= nsc; pA1.y *= nsc; pA1.z *= nsc; pA1.w *= nsc;
            pA2.x *= nsc; pA2.y *= nsc; pA2.z *= nsc; pA2.w *= nsc;
            pA1.x = tf32rn(pA1.x); pA1.y = tf32rn(pA1.y); pA1.z = tf32rn(pA1.z); pA1.w = tf32rn(pA1.w);
            pA2.x = tf32rn(pA2.x); pA2.y = tf32rn(pA2.y); pA2.z = tf32rn(pA2.z); pA2.w = tf32rn(pA2.w);
            *(float4*)&As[nxt][arow * ASTRIDE + ahalf * 8]     = pA1;
            *(float4*)&As[nxt][arow * ASTRIDE + ahalf * 8 + 4] = pA2;
            ((float4*)Bs[nxt])[t]       = pB1;
            ((float4*)Bs[nxt])[t + 256] = pB2;
        }
        __syncthreads();
    }

    // epilogue: bias + store
#pragma unroll
    for (int m2 = 0; m2 < 2; m2++) {
        const int row = bm + wm * 32 + m2 * 16 + (lane >> 2);
#pragma unroll
        for (int n8 = 0; n8 < 8; n8++) {
            const int cl = wn * 64 + n8 * 8 + (lane & 3) * 2;
            const float b0 = sBias[cl], b1 = sBias[cl + 1];
            float2 v0 = make_float2(acc[m2][n8][0] + b0, acc[m2][n8][1] + b1);
            float2 v1 = make_float2(acc[m2][n8][2] + b0, acc[m2][n8][3] + b1);
            *(float2*)&out[(size_t)row * 256 + bn + cl]       = v0;
            *(float2*)&out[(size_t)(row + 8) * 256 + bn + cl] = v1;
        }
    }
}

// ---------------------------------------------------------------------------
// Scatter: msg = gelu(x_l[src] + bond(edge_attr)) * w  -> atomicAdd sums[dst]
// ---------------------------------------------------------------------------
#define EPB 32
__global__ __launch_bounds__(256)
void scatter_kernel(const float* __restrict__ edge_attr,
                    const float* __restrict__ ew,
                    const float* __restrict__ bondW,
                    const float* __restrict__ bondb) {
    __shared__ float sBW[ED_ * C_];
    __shared__ float sEA[EPB][ED_];
    __shared__ int   sSrc[EPB];
    __shared__ int   sDst[EPB];
    __shared__ float sW[4][EPB];

    const int t  = threadIdx.x;
    const int e0 = blockIdx.x * EPB;

    for (int i = t; i < ED_ * C_; i += 256) sBW[i] = bondW[i];
    if (t < EPB) {
        int e = e0 + t;
        sSrc[t] = g_src[e];
        sDst[t] = g_dst[e];
#pragma unroll
        for (int rc = 0; rc < 4; rc++) sW[rc][t] = ew[(size_t)rc * EEDGES + e];
    }
    for (int i = t; i < EPB * ED_; i += 256)
        ((float*)sEA)[i] = edge_attr[(size_t)e0 * ED_ + i];
    __syncthreads();

    const int c = t;
    float bw[ED_];
#pragma unroll
    for (int k = 0; k < ED_; k++) bw[k] = sBW[k * C_ + c];
    const float bb = __ldg(&bondb[c]);

    for (int j = 0; j < EPB; j++) {
        float emb = bb;
#pragma unroll
        for (int k = 0; k < ED_; k++) emb = fmaf(sEA[j][k], bw[k], emb);
        const int src = sSrc[j];
        const int dst = sDst[j];
        if ((unsigned)src >= NNODES || (unsigned)dst >= NNODES) continue;
#pragma unroll
        for (int rc = 0; rc < 4; rc++) {
            size_t base = (size_t)rc * RCSLICE;
            float v = g_xl[base + (size_t)src * C_ + c] + emb;
            float g = 0.5f * v * (1.0f + erff(v * 0.70710678118654752f));
            atomicAdd(&g_sums[base + (size_t)dst * C_ + c], g * sW[rc][j]);
        }
    }
}

// ---------------------------------------------------------------------------
// Launch
// ---------------------------------------------------------------------------
extern "C" void kernel_launch(void* const* d_in, const int* in_sizes, int n_in,
                              void* d_out, int out_size) {
    const float* x     = (const float*)d_in[0];
    const float* eattr = (const float*)d_in[1];
    const float* ew    = (const float*)d_in[2];
    const float* linW  = (const float*)d_in[3];
    const float* linb  = (const float*)d_in[4];
    const float* linlW = (const float*)d_in[5];
    const float* linlb = (const float*)d_in[6];
    const float* linrW = (const float*)d_in[7];
    const float* bondW = (const float*)d_in[8];
    const float* bondb = (const float*)d_in[9];
    const int*   eidx  = (const int*)d_in[10];
    float*       out   = (float*)d_out;

    float *xl_p, *sums_p, *w0_p, *w1_p, *w2_p;
    cudaGetSymbolAddress((void**)&xl_p, g_xl);
    cudaGetSymbolAddress((void**)&sums_p, g_sums);
    cudaGetSymbolAddress((void**)&w0_p, g_w0fr);
    cudaGetSymbolAddress((void**)&w1_p, g_w1fr);
    cudaGetSymbolAddress((void**)&w2_p, g_w2fr);

    // 1. zero sums + counts (must precede convert's count atomics)
    {
        size_t n4 = (size_t)MROWS * C_ / 4;
        zero_kernel<<<(int)((n4 + 255) / 256), 256>>>();
    }

    // 0. index canonicalization + in-degree count
    detect_kernel<<<1, 32>>>(eidx);
    convert_idx_kernel<<<(EEDGES + 255) / 256, 256>>>(eidx);
    finalize_cnt_kernel<<<(NNODES + 255) / 256, 256>>>();

    // 2. weight prep (fragment order + tf32 round)
    prep_w_kernel<<<256, 256>>>(linW,  w0_p);
    prep_w_kernel<<<256, 256>>>(linlW, w1_p);
    prep_w_kernel<<<256, 256>>>(linrW, w2_p);

    // 3. x_l = x @ lin_W + lin_b   (mma.sync tf32)
    {
        dim3 grid(MROWS / 128, 2);
        mma_gemm_kernel<<<grid, 256>>>(x, w0_p, nullptr, nullptr, linb, xl_p, 0);
    }

    // 4. gather + bond-encode + gelu + weighted scatter-add
    scatter_kernel<<<EEDGES / EPB, 256>>>(eattr, ew, bondW, bondb);

    // 5. out = (sums/cnt) @ linl_W + linl_b + x @ linr_W   (K=512)
    {
        dim3 grid(MROWS / 128, 2);
        mma_gemm_kernel<<<grid, 256>>>(sums_p, w1_p, x, w2_p, linlb, out, 1);
    }
}

// round 10
// speedup vs baseline: 2.4995x; 1.2224x over previous
#include <cuda_runtime.h>
#include <math.h>
#include <stdint.h>

// Problem constants
#define R_      2
#define CH_     2
#define NNODES  20000
#define EEDGES  100000
#define C_      256
#define ED_     16
#define MROWS   (R_*CH_*NNODES)   // 80000
#define RCSLICE ((size_t)NNODES * C_)

// Scratch (static device globals; no allocation at runtime)
__device__ float g_xl[(size_t)MROWS * C_];    // x @ lin_W + lin_b
__device__ float g_sums[(size_t)MROWS * C_];  // scatter-add accumulator
__device__ float g_cnt[NNODES];
__device__ float g_invc[NNODES];
__device__ int   g_src[EEDGES];
__device__ int   g_dst[EEDGES];
__device__ int   g_is64;
// Fragment-ordered weight images for mma.sync tf32 B operand
__device__ float g_w0fr[256 * 256];  // lin_W
__device__ float g_w1fr[256 * 256];  // linl_W
__device__ float g_w2fr[256 * 256];  // linr_W

__device__ __forceinline__ float tf32rn(float x) {
    uint32_t r;
    asm("cvt.rna.tf32.f32 %0, %1;" : "=r"(r) : "f"(x));
    return __uint_as_float(r);
}

__device__ __forceinline__ void mma_tf32(float* d, const float* a, const float* b) {
    asm volatile(
        "mma.sync.aligned.m16n8k8.row.col.f32.tf32.tf32.f32 "
        "{%0,%1,%2,%3}, {%4,%5,%6,%7}, {%8,%9}, {%0,%1,%2,%3};\n"
        : "+f"(d[0]), "+f"(d[1]), "+f"(d[2]), "+f"(d[3])
        : "r"(__float_as_uint(a[0])), "r"(__float_as_uint(a[1])),
          "r"(__float_as_uint(a[2])), "r"(__float_as_uint(a[3])),
          "r"(__float_as_uint(b[0])), "r"(__float_as_uint(b[1])));
}

// ---------------------------------------------------------------------------
// edge_index dtype detection (JAX x64-off delivers int32 despite int64 request)
// ---------------------------------------------------------------------------
__global__ void detect_kernel(const int* __restrict__ eidx_raw) {
    if (threadIdx.x == 0 && blockIdx.x == 0) {
        int all_zero = 1;
        for (int i = 1; i < 64; i += 2)
            if (eidx_raw[i] != 0) { all_zero = 0; break; }
        g_is64 = all_zero;
    }
}
// convert + in-degree count fused
__global__ void convert_idx_kernel(const int* __restrict__ eidx_raw) {
    int e = blockIdx.x * blockDim.x + threadIdx.x;
    if (e >= EEDGES) return;
    int s, d;
    if (g_is64) {
        s = eidx_raw[2 * e];
        d = eidx_raw[2 * (EEDGES + e)];
    } else {
        s = eidx_raw[e];
        d = eidx_raw[EEDGES + e];
    }
    g_src[e] = s;
    g_dst[e] = d;
    if (d >= 0 && d < NNODES) atomicAdd(&g_cnt[d], 1.0f);
}

__global__ void zero_kernel() {
    size_t i = (size_t)blockIdx.x * blockDim.x + threadIdx.x;
    size_t n4 = (size_t)MROWS * C_ / 4;
    if (i < n4) ((float4*)g_sums)[i] = make_float4(0.f, 0.f, 0.f, 0.f);
    if (i < NNODES) g_cnt[i] = 0.f;
}
__global__ void finalize_cnt_kernel() {
    int n = blockIdx.x * blockDim.x + threadIdx.x;
    if (n < NNODES) g_invc[n] = 1.0f / fmaxf(g_cnt[n], 1.0f);
}

// ---------------------------------------------------------------------------
// Weight prep: W[k][n] (K=256 x N=256 row-major) -> mma B-fragment order.
// ---------------------------------------------------------------------------
__global__ void prep_w_kernel(const float* __restrict__ W, float* __restrict__ dst) {
    int e = blockIdx.x * blockDim.x + threadIdx.x;
    if (e >= 256 * 256) return;
    int n = e & 255, k = e >> 8;
    int nb = n >> 7, n_l = n & 127, natom = n_l >> 3, nr = n_l & 7;
    int k8 = k >> 3, kr = k & 7;
    int lane = nr * 4 + (kr & 3), reg = kr >> 2;
    int idx = (((nb * 32 + k8) * 16 + natom) * 32 + lane) * 2 + reg;
    dst[idx] = tf32rn(W[e]);
}

// ---------------------------------------------------------------------------
// mma.sync tf32 GEMM. CTA tile 128(M) x 128(N), 8 warps = 4m x 2n,
// warp tile 32x64, k-slab 16, double buffered.
// mode 0: out = A0 @ W0 + bias               (K=256)
// mode 1: out = (A0*invc) @ W0 + A1 @ W1 + bias   (K=512, two segments)
// ---------------------------------------------------------------------------
#define ASTRIDE 20   // floats per A smem row (16 + 4 pad, conflict-free quads)

__global__ __launch_bounds__(256, 2)
void mma_gemm_kernel(const float* __restrict__ A0, const float* __restrict__ W0fr,
                     const float* __restrict__ A1, const float* __restrict__ W1fr,
                     const float* __restrict__ bias, float* __restrict__ out, int mode) {
    __shared__ float As[2][128 * ASTRIDE];   // 20480 B
    __shared__ float Bs[2][2048];            // 16384 B
    __shared__ float sBias[128];

    const int t    = threadIdx.x;
    const int lane = t & 31;
    const int wid  = t >> 5;
    const int wm   = wid & 3;       // warp m index (0..3)
    const int wn   = wid >> 2;      // warp n index (0..1)
    const int bm   = blockIdx.x * 128;
    const int bn   = blockIdx.y * 128;
    const int nb   = blockIdx.y;    // n-block for fragment image

    if (t < 128) sBias[t] = bias[bn + t];

    const int arow  = t >> 1;       // 0..127
    const int ahalf = t & 1;        // which 8-k half of the 16-k slab

    float acc[2][8][4];
#pragma unroll
    for (int i = 0; i < 2; i++)
#pragma unroll
        for (int j = 0; j < 8; j++)
#pragma unroll
            for (int q = 0; q < 4; q++) acc[i][j][q] = 0.f;

    const int NK = mode ? 32 : 16;  // 16-k slabs total

    // prologue: slab 0
    {
        const float* Aseg = A0;
        const float* Wfr = W0fr;
        bool scaled = (mode == 1);
        const float* srcA = &Aseg[(size_t)(bm + arow) * 256 + ahalf * 8];
        float4 v1 = *(const float4*)(srcA);
        float4 v2 = *(const float4*)(srcA + 4);
        if (scaled) {
            float sc = g_invc[(bm + arow) % NNODES];
            v1.x *= sc; v1.y *= sc; v1.z *= sc; v1.w *= sc;
            v2.x *= sc; v2.y *= sc; v2.z *= sc; v2.w *= sc;
        }
        v1.x = tf32rn(v1.x); v1.y = tf32rn(v1.y); v1.z = tf32rn(v1.z); v1.w = tf32rn(v1.w);
        v2.x = tf32rn(v2.x); v2.y = tf32rn(v2.y); v2.z = tf32rn(v2.z); v2.w = tf32rn(v2.w);
        *(float4*)&As[0][arow * ASTRIDE + ahalf * 8]     = v1;
        *(float4*)&As[0][arow * ASTRIDE + ahalf * 8 + 4] = v2;
        const float4* srcB = (const float4*)&Wfr[(size_t)(nb * 32 + 0) * 1024];
        ((float4*)Bs[0])[t]       = srcB[t];
        ((float4*)Bs[0])[t + 256] = srcB[t + 256];
    }
    __syncthreads();

    for (int kt = 0; kt < NK; kt++) {
        const int cur = kt & 1;

        // prefetch next slab into registers
        float4 pA1, pA2, pB1, pB2;
        bool have_next = (kt + 1 < NK);
        float nsc = 1.0f;
        if (have_next) {
            int kn = kt + 1;
            int seg = (mode == 1) ? (kn >> 4) : 0;
            int ktl = (mode == 1) ? (kn & 15) : kn;
            const float* Aseg = (seg == 0) ? A0 : A1;
            const float* Wfr = (seg == 0) ? W0fr : W1fr;
            bool scaled = (mode == 1 && seg == 0);
            const float* srcA = &Aseg[(size_t)(bm + arow) * 256 + ktl * 16 + ahalf * 8];
            pA1 = *(const float4*)(srcA);
            pA2 = *(const float4*)(srcA + 4);
            if (scaled) nsc = g_invc[(bm + arow) % NNODES];
            const float4* srcB = (const float4*)&Wfr[(size_t)(nb * 32 + ktl * 2) * 1024];
            pB1 = srcB[t];
            pB2 = srcB[t + 256];
        }

        // compute on current buffer
#pragma unroll
        for (int ka = 0; ka < 2; ka++) {
            float bfr[8][2];
#pragma unroll
            for (int n8 = 0; n8 < 8; n8++) {
                const float2 bv = *(const float2*)&Bs[cur][((ka * 16 + wn * 8 + n8) * 32 + lane) * 2];
                bfr[n8][0] = bv.x; bfr[n8][1] = bv.y;
            }
#pragma unroll
            for (int m2 = 0; m2 < 2; m2++) {
                float afr[4];
                const int r0 = wm * 32 + m2 * 16 + (lane >> 2);
                const int k0 = ka * 8 + (lane & 3);
                afr[0] = As[cur][r0 * ASTRIDE + k0];
                afr[1] = As[cur][(r0 + 8) * ASTRIDE + k0];
                afr[2] = As[cur][r0 * ASTRIDE + k0 + 4];
                afr[3] = As[cur][(r0 + 8) * ASTRIDE + k0 + 4];
#pragma unroll
                for (int n8 = 0; n8 < 8; n8++)
                    mma_tf32(acc[m2][n8], afr, bfr[n8]);
            }
        }

        // store prefetched slab
        if (have_next) {
            const int nxt = cur ^ 1;
            pA1.x *= nsc; pA1.y *= nsc; pA1.z *= nsc; pA1.w *= nsc;
            pA2.x *= nsc; pA2.y *= nsc; pA2.z *= nsc; pA2.w *= nsc;
            pA1.x = tf32rn(pA1.x); pA1.y = tf32rn(pA1.y); pA1.z = tf32rn(pA1.z); pA1.w = tf32rn(pA1.w);
            pA2.x = tf32rn(pA2.x); pA2.y = tf32rn(pA2.y); pA2.z = tf32rn(pA2.z); pA2.w = tf32rn(pA2.w);
            *(float4*)&As[nxt][arow * ASTRIDE + ahalf * 8]     = pA1;
            *(float4*)&As[nxt][arow * ASTRIDE + ahalf * 8 + 4] = pA2;
            ((float4*)Bs[nxt])[t]       = pB1;
            ((float4*)Bs[nxt])[t + 256] = pB2;
        }
        __syncthreads();
    }

    // epilogue: bias + store
#pragma unroll
    for (int m2 = 0; m2 < 2; m2++) {
        const int row = bm + wm * 32 + m2 * 16 + (lane >> 2);
#pragma unroll
        for (int n8 = 0; n8 < 8; n8++) {
            const int cl = wn * 64 + n8 * 8 + (lane & 3) * 2;
            const float b0 = sBias[cl], b1 = sBias[cl + 1];
            float2 v0 = make_float2(acc[m2][n8][0] + b0, acc[m2][n8][1] + b1);
            float2 v1 = make_float2(acc[m2][n8][2] + b0, acc[m2][n8][3] + b1);
            *(float2*)&out[(size_t)row * 256 + bn + cl]       = v0;
            *(float2*)&out[(size_t)(row + 8) * 256 + bn + cl] = v1;
        }
    }
}

// ---------------------------------------------------------------------------
// Scatter: msg = gelu(x_l[src] + bond(edge_attr)) * w  -> red.v4 sums[dst]
// 256 threads = 64 channel-quads x 4 (r,ch) slices. Per edge each thread:
// one float4 gather, 4 GELUs, ONE red.global.add.v4.f32 (16B vector atomic).
// Bond embeddings precomputed per block into smem (phase 1).
// ---------------------------------------------------------------------------
#define EPB 32
__global__ __launch_bounds__(256)
void scatter_kernel(const float* __restrict__ edge_attr,
                    const float* __restrict__ ew,
                    const float* __restrict__ bondW,
                    const float* __restrict__ bondb) {
    __shared__ float sEmb[EPB][C_];      // 32 KB
    __shared__ float sEA[EPB][ED_];      // 2 KB
    __shared__ int   sSrc[EPB];
    __shared__ int   sDst[EPB];
    __shared__ float sW[4][EPB];

    const int t  = threadIdx.x;
    const int e0 = blockIdx.x * EPB;

    if (t < EPB) {
        int e = e0 + t;
        sSrc[t] = g_src[e];
        sDst[t] = g_dst[e];
#pragma unroll
        for (int rc = 0; rc < 4; rc++) sW[rc][t] = ew[(size_t)rc * EEDGES + e];
    }
    for (int i = t; i < EPB * ED_; i += 256)
        ((float*)sEA)[i] = edge_attr[(size_t)e0 * ED_ + i];
    __syncthreads();

    // phase 1: bond embeddings for all EPB edges x 256 channels
    for (int i = t; i < EPB * C_; i += 256) {
        const int j = i >> 8;       // edge in block
        const int c = i & 255;      // channel
        float emb = __ldg(&bondb[c]);
#pragma unroll
        for (int k = 0; k < ED_; k++)
            emb = fmaf(sEA[j][k], __ldg(&bondW[k * C_ + c]), emb);
        sEmb[j][c] = emb;
    }
    __syncthreads();

    // phase 2: gather + gelu + vector reduction
    const int q  = (t & 63) * 4;    // channel quad base (0..252)
    const int rc = t >> 6;          // (r,ch) slice 0..3
    const size_t base = (size_t)rc * RCSLICE;
    const float* wrow = sW[rc];

    for (int j = 0; j < EPB; j++) {
        const int src = sSrc[j];
        const int dst = sDst[j];
        if ((unsigned)src >= NNODES || (unsigned)dst >= NNODES) continue;
        const float w = wrow[j];
        float4 xv = *(const float4*)&g_xl[base + (size_t)src * C_ + q];
        const float4 ev = *(const float4*)&sEmb[j][q];
        float4 g;
        float v;
        v = xv.x + ev.x; g.x = 0.5f * v * (1.0f + erff(v * 0.70710678118654752f)) * w;
        v = xv.y + ev.y; g.y = 0.5f * v * (1.0f + erff(v * 0.70710678118654752f)) * w;
        v = xv.z + ev.z; g.z = 0.5f * v * (1.0f + erff(v * 0.70710678118654752f)) * w;
        v = xv.w + ev.w; g.w = 0.5f * v * (1.0f + erff(v * 0.70710678118654752f)) * w;
        float* dp = &g_sums[base + (size_t)dst * C_ + q];
        asm volatile("red.global.add.v4.f32 [%0], {%1,%2,%3,%4};"
                     :: "l"(dp), "f"(g.x), "f"(g.y), "f"(g.z), "f"(g.w)
                     : "memory");
    }
}

// ---------------------------------------------------------------------------
// Launch
// ---------------------------------------------------------------------------
extern "C" void kernel_launch(void* const* d_in, const int* in_sizes, int n_in,
                              void* d_out, int out_size) {
    const float* x     = (const float*)d_in[0];
    const float* eattr = (const float*)d_in[1];
    const float* ew    = (const float*)d_in[2];
    const float* linW  = (const float*)d_in[3];
    const float* linb  = (const float*)d_in[4];
    const float* linlW = (const float*)d_in[5];
    const float* linlb = (const float*)d_in[6];
    const float* linrW = (const float*)d_in[7];
    const float* bondW = (const float*)d_in[8];
    const float* bondb = (const float*)d_in[9];
    const int*   eidx  = (const int*)d_in[10];
    float*       out   = (float*)d_out;

    float *xl_p, *sums_p, *w0_p, *w1_p, *w2_p;
    cudaGetSymbolAddress((void**)&xl_p, g_xl);
    cudaGetSymbolAddress((void**)&sums_p, g_sums);
    cudaGetSymbolAddress((void**)&w0_p, g_w0fr);
    cudaGetSymbolAddress((void**)&w1_p, g_w1fr);
    cudaGetSymbolAddress((void**)&w2_p, g_w2fr);

    // 1. zero sums + counts (must precede convert's count atomics)
    {
        size_t n4 = (size_t)MROWS * C_ / 4;
        zero_kernel<<<(int)((n4 + 255) / 256), 256>>>();
    }

    // 0. index canonicalization + in-degree count
    detect_kernel<<<1, 32>>>(eidx);
    convert_idx_kernel<<<(EEDGES + 255) / 256, 256>>>(eidx);
    finalize_cnt_kernel<<<(NNODES + 255) / 256, 256>>>();

    // 2. weight prep (fragment order + tf32 round)
    prep_w_kernel<<<256, 256>>>(linW,  w0_p);
    prep_w_kernel<<<256, 256>>>(linlW, w1_p);
    prep_w_kernel<<<256, 256>>>(linrW, w2_p);

    // 3. x_l = x @ lin_W + lin_b   (mma.sync tf32)
    {
        dim3 grid(MROWS / 128, 2);
        mma_gemm_kernel<<<grid, 256>>>(x, w0_p, nullptr, nullptr, linb, xl_p, 0);
    }

    // 4. gather + bond-encode + gelu + weighted scatter-add (vector atomics)
    scatter_kernel<<<EEDGES / EPB, 256>>>(eattr, ew, bondW, bondb);

    // 5. out = (sums/cnt) @ linl_W + linl_b + x @ linr_W   (K=512)
    {
        dim3 grid(MROWS / 128, 2);
        mma_gemm_kernel<<<grid, 256>>>(sums_p, w1_p, x, w2_p, linlb, out, 1);
    }
}